// round 14
// baseline (speedup 1.0000x reference)
#include <cuda_runtime.h>
#include <stdint.h>

#define H 2048
#define W 2048
#define KS 11
#define PS 10
#define PAD 5
#define HO 205                 // conv output: floor((2048+10-11)/10)+1
#define OUT 2255               // 205 * (PS+1)

// Intermediate per-cell result: [3][HO][HO] (+pad for safe over-read)
__device__ float g_mid[3 * HO * HO + 8];
// Per-row completion counters (zeroed by a memset node each replay)
__device__ int g_cnt[HO];

// ---------------------------------------------------------------------------
// Fused kernel. Grid (26, 205), 256 threads.
// Phase 1 (all blocks): 8 warps = 8 cells of mid-row oh (R10 body, measured
//   fastest: batched LDG MLP=12, packed histogram + redux, lane-parallel
//   argmax with jnp first-max tie-break, 16.16 fixed-point masked sums).
// Phase 2 (one block per row — the one whose atomicAdd completes the row):
//   upsample band oh for all 3 channels (33 output rows) with the proven
//   R4 row body. threadFenceReduction pattern: no spinning, no deadlock.
// ---------------------------------------------------------------------------
__global__ void __launch_bounds__(256) fused_kernel(const float* __restrict__ rgb,
                                                    float* __restrict__ out) {
    const int oh  = blockIdx.y;
    const int ow0 = blockIdx.x * 8;
    const int tid = threadIdx.x;
    const int w   = tid >> 5;
    const int lane = tid & 31;
    const int ow  = ow0 + w;
    __shared__ int amLast;

    if (ow < HO) {
        const int wid = oh * HO + ow;
        const int y0 = oh * PS - PAD;
        const int x0 = ow * PS - PAD;
        const bool border = (oh == 0) | (ow == 0);   // warp-uniform

        const float* __restrict__ rp = rgb;
        const float* __restrict__ gp = rgb + H * W;
        const float* __restrict__ bp = rgb + 2 * H * W;

        int off[4];
        bool act[4];
        act[0] = true; act[1] = true; act[2] = true; act[3] = (lane < 25);
#pragma unroll
        for (int t = 0; t < 4; t++) {
            int p = lane + t * 32;
            if (t == 3) p = p > 120 ? 120 : p;       // dup load, masked later
            const int dy = p / KS;
            const int dx = p - dy * KS;
            off[t] = (y0 + dy) * W + (x0 + dx);
            if (border)
                act[t] = act[t] && (y0 + dy >= 0) && (x0 + dx >= 0);
        }

        // Batch ALL loads before any consumer (MLP=12 — measured critical).
        float rv[4], gv[4], bv[4];
        if (!border) {
#pragma unroll
            for (int t = 0; t < 4; t++) rv[t] = __ldg(rp + off[t]);
#pragma unroll
            for (int t = 0; t < 4; t++) gv[t] = __ldg(gp + off[t]);
#pragma unroll
            for (int t = 0; t < 4; t++) bv[t] = __ldg(bp + off[t]);
        } else {
#pragma unroll
            for (int t = 0; t < 4; t++) rv[t] = act[t] ? __ldg(rp + off[t]) : 0.0f;
#pragma unroll
            for (int t = 0; t < 4; t++) gv[t] = act[t] ? __ldg(gp + off[t]) : 0.0f;
#pragma unroll
            for (int t = 0; t < 4; t++) bv[t] = act[t] ? __ldg(bp + off[t]) : 0.0f;
        }

        // Bin + packed histogram (8-bit counters; totals <=121: carry-free).
        int bn[4];
        unsigned long long hlo = 0ULL, hhi = 0ULL;
#pragma unroll
        for (int t = 0; t < 4; t++) {
            const float s = __fadd_rn(__fadd_rn(rv[t], gv[t]), bv[t]);
            const int bi = (int)(__fmul_rn(s, 0.020833334f));   // 1/48 rn
            bn[t] = act[t] ? bi : 16;                            // 16 = dead
            if (act[t]) {
                const unsigned long long inc = 1ULL << ((bi & 7) * 8);
                if (bi < 8) hlo += inc; else hhi += inc;
            }
        }

        const unsigned h0 = __reduce_add_sync(0xffffffffu, (unsigned)hlo);
        const unsigned h1 = __reduce_add_sync(0xffffffffu, (unsigned)(hlo >> 32));
        const unsigned h2 = __reduce_add_sync(0xffffffffu, (unsigned)hhi);
        const unsigned h3 = __reduce_add_sync(0xffffffffu, (unsigned)(hhi >> 32));

        // Lane-parallel argmax; ties -> smaller bin (jnp.argmax first-max).
        const int b = lane & 15;
        const unsigned hw = (b < 8) ? ((b < 4) ? h0 : h1) : ((b < 12) ? h2 : h3);
        const unsigned cnt = (hw >> ((b & 3) * 8)) & 0xFFu;
        const unsigned key = (cnt << 4) | (unsigned)(15 - b);
        const unsigned kmax = __reduce_max_sync(0xffffffffu, key);
        const int amax = 15 - (int)(kmax & 15u);
        const float cm = (float)(kmax >> 4);

        // Masked channel sums in 16.16 fixed point (sum < 2^31; err ~1e-7 rel).
        int sri = 0, sgi = 0, sbi = 0;
#pragma unroll
        for (int t = 0; t < 4; t++) {
            if (bn[t] == amax) {
                sri += (int)(rv[t] * 65536.0f);
                sgi += (int)(gv[t] * 65536.0f);
                sbi += (int)(bv[t] * 65536.0f);
            }
        }
        const unsigned sru = __reduce_add_sync(0xffffffffu, (unsigned)sri);
        const unsigned sgu = __reduce_add_sync(0xffffffffu, (unsigned)sgi);
        const unsigned sbu = __reduce_add_sync(0xffffffffu, (unsigned)sbi);

        if (lane == 0) {
            const float inv = __fmul_rn(__frcp_rn(cm), 1.52587890625e-05f);
            g_mid[wid]               = __fmul_rn((float)sru, inv);
            g_mid[wid + HO * HO]     = __fmul_rn((float)sgu, inv);
            g_mid[wid + 2 * HO * HO] = __fmul_rn((float)sbu, inv);
        }
    }

    // ---- row-completion handshake (threadFenceReduction pattern) ----
    __syncthreads();
    if (tid == 0) {
        __threadfence();                            // publish g_mid stores
        const int nact = (ow0 + 8 <= HO) ? 8 : (HO - ow0);
        const int old = atomicAdd(&g_cnt[oh], nact);
        amLast = (old + nact == HO) ? 1 : 0;
    }
    __syncthreads();
    if (!amLast) return;

    // ---- Phase 2: upsample band oh, all 3 channels (33 rows) — R4 body ----
    for (int rr = 0; rr < 33; rr++) {
        const int c = rr / 11;
        const int r = rr - c * 11;
        const size_t rowbase = ((size_t)c * OUT + (size_t)(oh * 11 + r)) * OUT;
        float* __restrict__ orow = out + rowbase;
        const int h = (int)((4u - ((unsigned)rowbase & 3u)) & 3u);
        const int nv = (OUT - h) >> 2;              // 563
        const int nt = OUT - h - nv * 4;
        float4* __restrict__ ov = (float4*)(orow + h);

        if (r == 10) {                              // pad row: zeros
            if (tid < h) orow[tid] = 0.0f;
            if (tid >= 4 && tid < 4 + nt) orow[h + nv * 4 + (tid - 4)] = 0.0f;
            const float4 z = make_float4(0.f, 0.f, 0.f, 0.f);
            for (int v = tid; v < nv; v += 256) ov[v] = z;
            continue;
        }

        const float* __restrict__ midc = g_mid + c * (HO * HO) + oh * HO;

        if (tid < h) orow[tid] = __ldg(midc);       // x<=2: ow=0, j<10
        if (tid >= 4 && tid < 4 + nt) {
            const unsigned x = (unsigned)(h + nv * 4 + (tid - 4));
            const unsigned o = x / 11u;
            const unsigned j = x - o * 11u;
            orow[x] = (j < 10u) ? __ldg(midc + o) : 0.0f;
        }

        for (int v = tid; v < nv; v += 256) {
            const unsigned x0 = (unsigned)(h + v * 4);
            float4 o;
            float* po = &o.x;
#pragma unroll
            for (int k = 0; k < 4; k++) {
                const unsigned x = x0 + (unsigned)k;
                const unsigned o2 = x / 11u;
                const unsigned j = x - o2 * 11u;
                po[k] = (j < 10u) ? __ldg(midc + o2) : 0.0f;
            }
            ov[v] = o;
        }
    }
}

extern "C" void kernel_launch(void* const* d_in, const int* in_sizes, int n_in,
                              void* d_out, int out_size) {
    const float* rgb = (const float*)d_in[0];
    float* out = (float*)d_out;

    // Zero per-row counters (graph-capturable memset node, runs each replay)
    void* cnt_ptr = nullptr;
    cudaGetSymbolAddress(&cnt_ptr, g_cnt);
    cudaMemsetAsync(cnt_ptr, 0, HO * sizeof(int), 0);

    dim3 grid(26, HO);                              // 26 x 205 blocks
    fused_kernel<<<grid, 256>>>(rgb, out);
}

// round 15
// speedup vs baseline: 2.3875x; 2.3875x over previous
#include <cuda_runtime.h>
#include <stdint.h>

#define H 2048
#define W 2048
#define KS 11
#define PS 10
#define PAD 5
#define HO 205                 // conv output: floor((2048+10-11)/10)+1
#define OUT 2255               // 205 * (PS+1)
#define CELLS (HO*HO)
#define ROWS_TOTAL (3*OUT)

// Intermediate per-cell result: [3][HO][HO] (+pad for safe over-read)
__device__ float g_mid[3 * HO * HO + 8];

// ---------------------------------------------------------------------------
// Kernel 1: one warp per output cell — EXACT R5 body (best measured: 15.39us).
// 16-bin histogram of the 11x11 window (packed 8-bit counters), argmax bin
// via single warp-reduce-max (first-max tie-break like jnp.argmax),
// per-channel mean of pixels in that bin via float shfl-xor sums.
// ---------------------------------------------------------------------------
__global__ void __launch_bounds__(256) cell_kernel(const float* __restrict__ rgb) {
    const int wid = (blockIdx.x * blockDim.x + threadIdx.x) >> 5;
    if (wid >= CELLS) return;
    const int lane = threadIdx.x & 31;

    const int oh = wid / HO;
    const int ow = wid - oh * HO;
    const int y0 = oh * PS - PAD;
    const int x0 = ow * PS - PAD;

    const float* __restrict__ rp = rgb;
    const float* __restrict__ gp = rgb + H * W;
    const float* __restrict__ bp = rgb + 2 * H * W;

    // p = lane + 32t; window is 121 px: t=0..2 always active, t=3 iff lane<25.
    int off[4];
    bool act[4];
    act[0] = true; act[1] = true; act[2] = true; act[3] = (lane < 25);
#pragma unroll
    for (int t = 0; t < 4; t++) {
        const int p = lane + t * 32;
        const int dy = p / KS;
        const int dx = p - dy * KS;
        off[t] = (y0 + dy) * W + (x0 + dx);
    }
    if ((oh == 0) | (ow == 0)) {   // border cells: 409 of 42025
#pragma unroll
        for (int t = 0; t < 4; t++) {
            const int p = lane + t * 32;
            const int dy = p / KS;
            const int dx = p - dy * KS;
            act[t] = act[t] && (y0 + dy >= 0) && (x0 + dx >= 0);
        }
    }

    // Batch all loads first (max MLP); inactive slots hold 0.
    float rv[4], gv[4], bv[4];
#pragma unroll
    for (int t = 0; t < 4; t++) rv[t] = act[t] ? __ldg(rp + off[t]) : 0.0f;
#pragma unroll
    for (int t = 0; t < 4; t++) gv[t] = act[t] ? __ldg(gp + off[t]) : 0.0f;
#pragma unroll
    for (int t = 0; t < 4; t++) bv[t] = act[t] ? __ldg(bp + off[t]) : 0.0f;

    // Bin + packed histogram (bins 0-7 in hlo, 8-15 in hhi; 8-bit counters,
    // per-bin totals <= 121 < 256 so the warp reduction is carry-free)
    int bn[4];
    unsigned long long hlo = 0ULL, hhi = 0ULL;
#pragma unroll
    for (int t = 0; t < 4; t++) {
        // bin = floor(mean(r,g,b)/256*16) = floor((r+g+b)*(1/3)*2^-4)
        const float s = __fadd_rn(__fadd_rn(rv[t], gv[t]), bv[t]);
        const float m = __fmul_rn(s, 0.3333333432674408f);   // 1/3 rn
        const int bi = (int)(__fmul_rn(m, 0.0625f));          // in [0,15]
        bn[t] = bi;
        if (act[t]) {
            const unsigned long long inc = 1ULL << ((bi & 7) * 8);
            if (bi < 8) hlo += inc; else hhi += inc;
        }
    }

    const unsigned h0 = __reduce_add_sync(0xffffffffu, (unsigned)hlo);
    const unsigned h1 = __reduce_add_sync(0xffffffffu, (unsigned)(hlo >> 32));
    const unsigned h2 = __reduce_add_sync(0xffffffffu, (unsigned)hhi);
    const unsigned h3 = __reduce_add_sync(0xffffffffu, (unsigned)(hhi >> 32));

    // Lane-parallel argmax: lane (b = lane&15) owns bin b.
    // key = (cnt<<4) | (15-b): ties -> smaller bin wins (jnp.argmax).
    const int b = lane & 15;
    const unsigned hw = (b < 8) ? ((b < 4) ? h0 : h1) : ((b < 12) ? h2 : h3);
    const unsigned cnt = (hw >> ((b & 3) * 8)) & 0xFFu;
    const unsigned key = (cnt << 4) | (unsigned)(15 - b);
    const unsigned kmax = __reduce_max_sync(0xffffffffu, key);
    const int amax = 15 - (int)(kmax & 15u);
    const float cm = (float)(kmax >> 4);

    // Masked per-channel sums (inactive slots hold 0.0)
    float sr = 0.f, sg = 0.f, sb = 0.f;
#pragma unroll
    for (int t = 0; t < 4; t++) {
        if (bn[t] == amax) { sr += rv[t]; sg += gv[t]; sb += bv[t]; }
    }
#pragma unroll
    for (int s = 16; s > 0; s >>= 1) {
        sr += __shfl_xor_sync(0xffffffffu, sr, s);
        sg += __shfl_xor_sync(0xffffffffu, sg, s);
        sb += __shfl_xor_sync(0xffffffffu, sb, s);
    }

    if (lane == 0) {
        const float inv = __frcp_rn(cm);
        g_mid[wid]               = __fmul_rn(sr, inv);
        g_mid[wid + HO * HO]     = __fmul_rn(sg, inv);
        g_mid[wid + 2 * HO * HO] = __fmul_rn(sb, inv);
    }
}

// ---------------------------------------------------------------------------
// Kernel 2: upsample 205x205 -> 2255x2255 per channel — EXACT R4 body
// (best measured: 12.64us). One 128-thread block per output row,
// branch-free magic-div indexing, aligned float4 stores.
// ---------------------------------------------------------------------------
__global__ void __launch_bounds__(128) upsample_kernel(float* __restrict__ out) {
    const int row = blockIdx.x;            // 0 .. 3*2255-1
    const int tid = threadIdx.x;
    const unsigned ur = (unsigned)row;
    const unsigned c = ur / (unsigned)OUT;
    const unsigned y = ur - c * (unsigned)OUT;
    const unsigned oh = y / 11u;
    const unsigned ii = y - oh * 11u;

    float* __restrict__ orow = out + (size_t)row * OUT;
    const int h = (int)((4u - ((ur * (unsigned)OUT) & 3u)) & 3u);
    const int nv = (OUT - h) >> 2;
    const int nt = OUT - h - nv * 4;
    float4* __restrict__ ov = (float4*)(orow + h);

    if (ii == 10u) {                       // pad row: zeros
        if (tid < h) orow[tid] = 0.0f;
        if (tid >= 4 && tid < 4 + nt) orow[h + nv * 4 + (tid - 4)] = 0.0f;
        const float4 z = make_float4(0.f, 0.f, 0.f, 0.f);
        for (int v = tid; v < nv; v += 128) ov[v] = z;
        return;
    }

    const float* __restrict__ midc = g_mid + c * HO * HO + oh * HO;

    // Scalar head (x <= 2: o=0, j<10 -> always live)
    if (tid < h) orow[tid] = __ldg(midc);
    // Scalar tail (x in 2252..2254)
    if (tid >= 4 && tid < 4 + nt) {
        const unsigned x = (unsigned)(h + nv * 4 + (tid - 4));
        const unsigned o = x / 11u;
        const unsigned j = x - o * 11u;
        orow[x] = (j < 10u) ? __ldg(midc + o) : 0.0f;
    }

    // Vector body: 4 independent magic-divs per float4, no divergence
    for (int v = tid; v < nv; v += 128) {
        const unsigned x0 = (unsigned)(h + v * 4);
        float4 o;
        float* po = &o.x;
#pragma unroll
        for (int k = 0; k < 4; k++) {
            const unsigned x = x0 + (unsigned)k;
            const unsigned ow = x / 11u;
            const unsigned j = x - ow * 11u;
            po[k] = (j < 10u) ? __ldg(midc + ow) : 0.0f;
        }
        ov[v] = o;
    }
}

extern "C" void kernel_launch(void* const* d_in, const int* in_sizes, int n_in,
                              void* d_out, int out_size) {
    const float* rgb = (const float*)d_in[0];
    float* out = (float*)d_out;

    const int blocks1 = (CELLS + 7) / 8;       // one warp per cell, 8/block
    cell_kernel<<<blocks1, 256>>>(rgb);

    upsample_kernel<<<ROWS_TOTAL, 128>>>(out); // one block per output row
}